// round 15
// baseline (speedup 1.0000x reference)
#include <cuda_runtime.h>
#include <cuda_bf16.h>
#include <math.h>
#include <stdint.h>

typedef unsigned long long u64;
typedef unsigned int u32;
typedef unsigned short u16;

#define Nn 8192
#define NCH 64
#define NTRI (NCH * (NCH + 1) / 2)
#define NOFF (NCH * (NCH - 1) / 2)      // 2016 strictly-lower tiles
#define NBLK (NCH * NCH + 2 * NTRI)     // 8256 tiles
#define NCOMB 128                        // combine blocks appended to softmin grid
#define L2E 1.44269504088896f
#define LN2 0.69314718055995f

// ---------------- static scratch ----------------
__device__ u16 d_Cxy[(u64)Nn * Nn];
__device__ u16 d_Cxx[(u64)Nn * Nn];
__device__ u16 d_Cyy[(u64)Nn * Nn];
__device__ __nv_bfloat16 d_Xh[(u64)Nn * 64], d_Xl[(u64)Nn * 64];
__device__ __nv_bfloat16 d_Yh[(u64)Nn * 64], d_Yl[(u64)Nn * 64];
__device__ float d_sqx[Nn], d_sqy[Nn];
__device__ float d_scales[6];
__device__ float d_faa[Nn], d_gbb[Nn], d_gab[Nn], d_fba[Nn];
__device__ float d_tft[Nn], d_tgt[Nn], d_tftaa[Nn], d_tgtbb[Nn];
__device__ float d_pRM[(u64)NCH * Nn], d_pRS[(u64)NCH * Nn];
__device__ float d_pCM[(u64)NCH * Nn], d_pCS[(u64)NCH * Nn];
__device__ float d_pXM[(u64)NCH * Nn], d_pXS[(u64)NCH * Nn];
__device__ float d_pYM[(u64)NCH * Nn], d_pYS[(u64)NCH * Nn];
__device__ int d_cnt;     // tiles completed this round
__device__ int d_cnt2;    // combine blocks past the spin

__device__ __forceinline__ float ex2(float x) {
    float r; asm("ex2.approx.ftz.f32 %0, %1;" : "=f"(r) : "f"(x)); return r;
}
__device__ __forceinline__ float lg2(float x) {
    float r; asm("lg2.approx.f32 %0, %1;" : "=f"(r) : "f"(x)); return r;
}
// strictly-lower tiles first (i < NOFF), diagonals last
__device__ __forceinline__ void sym_decode(int i, int& by, int& bx) {
    if (i < NOFF) {
        int r = (int)((1.0f + sqrtf(1.0f + 8.0f * (float)i)) * 0.5f);
        while ((r + 1) * r / 2 <= i) ++r;
        while (r * (r - 1) / 2 > i) --r;
        by = r; bx = i - r * (r - 1) / 2;
    } else {
        by = bx = i - NOFF;
    }
}
__device__ __forceinline__ float q2f_lo(u32 a) {
    return __uint_as_float(__byte_perm(a, 0x4B000000u, 0x7410));
}
__device__ __forceinline__ float q2f_hi(u32 a) {
    return __uint_as_float(__byte_perm(a, 0x4B000000u, 0x7432));
}
__device__ __forceinline__ void ldsm4(u32& r0, u32& r1, u32& r2, u32& r3, u32 addr) {
    asm volatile("ldmatrix.sync.aligned.m8n8.x4.shared.b16 {%0,%1,%2,%3}, [%4];"
                 : "=r"(r0), "=r"(r1), "=r"(r2), "=r"(r3) : "r"(addr));
}
__device__ __forceinline__ void mma16816(float* d, const u32* a, u32 b0, u32 b1) {
    asm volatile(
        "mma.sync.aligned.m16n8k16.row.col.f32.bf16.bf16.f32 "
        "{%0,%1,%2,%3}, {%4,%5,%6,%7}, {%8,%9}, {%0,%1,%2,%3};"
        : "+f"(d[0]), "+f"(d[1]), "+f"(d[2]), "+f"(d[3])
        : "r"(a[0]), "r"(a[1]), "r"(a[2]), "r"(a[3]), "r"(b0), "r"(b1));
}

// ---------------- prep: sqnorm + bf16 hi/lo split for X and Y ----------------
__global__ void prep_kernel(const float* __restrict__ X, const float* __restrict__ Y,
                            float* __restrict__ sqx, float* __restrict__ sqy,
                            __nv_bfloat16* __restrict__ Xh, __nv_bfloat16* __restrict__ Xl,
                            __nv_bfloat16* __restrict__ Yh, __nv_bfloat16* __restrict__ Yl)
{
    int gw   = (blockIdx.x * blockDim.x + threadIdx.x) >> 5;
    int lane = threadIdx.x & 31;
    int row  = gw & 8191;
    const float* src = (gw < 8192) ? X : Y;
    float* sq = (gw < 8192) ? sqx : sqy;
    __nv_bfloat16* hi = (gw < 8192) ? Xh : Yh;
    __nv_bfloat16* lo = (gw < 8192) ? Xl : Yl;

    float a = src[(u64)row * 64 + lane];
    float b = src[(u64)row * 64 + lane + 32];
    __nv_bfloat16 ha = __float2bfloat16(a), hb = __float2bfloat16(b);
    hi[(u64)row * 64 + lane]      = ha;
    hi[(u64)row * 64 + lane + 32] = hb;
    lo[(u64)row * 64 + lane]      = __float2bfloat16(a - __bfloat162float(ha));
    lo[(u64)row * 64 + lane + 32] = __float2bfloat16(b - __bfloat162float(hb));
    float s = a * a + b * b;
    #pragma unroll
    for (int o = 16; o; o >>= 1) s += __shfl_xor_sync(0xffffffffu, s, o);
    if (lane == 0) sq[row] = 0.5f * s;
}

// ---------------- global quantization scales ----------------
__global__ void scale_kernel(const float* __restrict__ sqx, const float* __restrict__ sqy,
                             float* __restrict__ scales) {
    __shared__ float red[16];
    int tid = threadIdx.x, lane = tid & 31, w = tid >> 5;
    float mx = 0.f, my = 0.f;
    for (int i = tid; i < Nn; i += 256) {
        mx = fmaxf(mx, sqx[i]);
        my = fmaxf(my, sqy[i]);
    }
    #pragma unroll
    for (int o = 16; o; o >>= 1) {
        mx = fmaxf(mx, __shfl_xor_sync(0xffffffffu, mx, o));
        my = fmaxf(my, __shfl_xor_sync(0xffffffffu, my, o));
    }
    if (lane == 0) { red[w] = mx; red[w + 8] = my; }
    __syncthreads();
    if (tid == 0) {
        float MX = red[0], MY = red[8];
        #pragma unroll
        for (int i = 1; i < 8; ++i) { MX = fmaxf(MX, red[i]); MY = fmaxf(MY, red[8 + i]); }
        float cxy = MX + MY + 2.0f * sqrtf(MX * MY);
        scales[0] = cxy / 65500.0f;       scales[3] = 65500.0f / cxy;
        scales[1] = 4.0f * MX / 65500.0f; scales[4] = 65500.0f / (4.0f * MX);
        scales[2] = 4.0f * MY / 65500.0f; scales[5] = 65500.0f / (4.0f * MY);
    }
}

// ---------------- merged tensor-core cost GEMM (all three matrices, one launch) -----
__global__ void __launch_bounds__(256, 2) mma_gemm_all_kernel(
    const __nv_bfloat16* __restrict__ Xh, const __nv_bfloat16* __restrict__ Xl,
    const __nv_bfloat16* __restrict__ Yh, const __nv_bfloat16* __restrict__ Yl,
    const float* __restrict__ sqx, const float* __restrict__ sqy,
    const float* __restrict__ scales,
    u16* __restrict__ Cxy, u16* __restrict__ Cxx, u16* __restrict__ Cyy)
{
    int b = blockIdx.x;
    int which, bxi, byi;
    if (b < NCH * NCH) { which = 0; byi = b >> 6; bxi = b & 63; }
    else if (b < NCH * NCH + NTRI) { which = 1; sym_decode(b - NCH * NCH, byi, bxi); }
    else { which = 2; sym_decode(b - NCH * NCH - NTRI, byi, bxi); }

    const __nv_bfloat16* Ah_g = (which == 2) ? Yh : Xh;
    const __nv_bfloat16* Al_g = (which == 2) ? Yl : Xl;
    const __nv_bfloat16* Bh_g = (which == 1) ? Xh : Yh;
    const __nv_bfloat16* Bl_g = (which == 1) ? Xl : Yl;
    const float* sqa = (which == 2) ? sqy : sqx;
    const float* sqb = (which == 1) ? sqx : sqy;
    const float inv = scales[3 + which];
    u16* Cq = (which == 0) ? Cxy : (which == 1) ? Cxx : Cyy;

    const int bi = byi * 128, bj = bxi * 128;
    extern __shared__ __nv_bfloat16 sh[];
    __nv_bfloat16* sAh = sh;
    __nv_bfloat16* sAl = sh + 8192;
    __nv_bfloat16* sBh = sh + 16384;
    __nv_bfloat16* sBl = sh + 24576;
    const int tid = threadIdx.x;

    #pragma unroll
    for (int i = 0; i < 4; ++i) {
        int idx = tid + i * 256;
        int r = idx >> 3, c = idx & 7;
        int sc = c ^ (r & 7);
        ((uint4*)sAh)[r * 8 + sc] = *(const uint4*)(Ah_g + (u64)(bi + r) * 64 + c * 8);
        ((uint4*)sAl)[r * 8 + sc] = *(const uint4*)(Al_g + (u64)(bi + r) * 64 + c * 8);
        ((uint4*)sBh)[r * 8 + sc] = *(const uint4*)(Bh_g + (u64)(bj + r) * 64 + c * 8);
        ((uint4*)sBl)[r * 8 + sc] = *(const uint4*)(Bl_g + (u64)(bj + r) * 64 + c * 8);
    }
    __syncthreads();

    const int w = tid >> 5, lane = tid & 31;
    const int mw = (w & 3) * 32, nw = (w >> 2) * 64;
    const int lq = lane >> 3, lr = lane & 7;
    const u32 baseAh = (u32)__cvta_generic_to_shared(sAh);
    const u32 baseAl = (u32)__cvta_generic_to_shared(sAl);
    const u32 baseBh = (u32)__cvta_generic_to_shared(sBh);
    const u32 baseBl = (u32)__cvta_generic_to_shared(sBl);

    float acc[2][8][4];
    #pragma unroll
    for (int mi = 0; mi < 2; ++mi)
        #pragma unroll
        for (int ni = 0; ni < 8; ++ni)
            #pragma unroll
            for (int e = 0; e < 4; ++e) acc[mi][ni][e] = 0.f;

    #pragma unroll
    for (int ks = 0; ks < 4; ++ks) {
        const int ch = ks * 2 + (lq >> 1);
        u32 ah[2][4], al[2][4];
        #pragma unroll
        for (int mi = 0; mi < 2; ++mi) {
            int row = mw + mi * 16 + (lq & 1) * 8 + lr;
            u32 off = (u32)(row * 128 + ((ch ^ (row & 7)) << 4));
            ldsm4(ah[mi][0], ah[mi][1], ah[mi][2], ah[mi][3], baseAh + off);
            ldsm4(al[mi][0], al[mi][1], al[mi][2], al[mi][3], baseAl + off);
        }
        u32 bh[4][4], bl[4][4];
        #pragma unroll
        for (int nj = 0; nj < 4; ++nj) {
            int row = nw + nj * 16 + (lq & 1) * 8 + lr;
            u32 off = (u32)(row * 128 + ((ch ^ (row & 7)) << 4));
            ldsm4(bh[nj][0], bh[nj][1], bh[nj][2], bh[nj][3], baseBh + off);
            ldsm4(bl[nj][0], bl[nj][1], bl[nj][2], bl[nj][3], baseBl + off);
        }
        #pragma unroll
        for (int mi = 0; mi < 2; ++mi)
            #pragma unroll
            for (int ni = 0; ni < 8; ++ni) {
                int nj = ni >> 1;
                u32 h0 = (ni & 1) ? bh[nj][1] : bh[nj][0];
                u32 h1 = (ni & 1) ? bh[nj][3] : bh[nj][2];
                u32 l0 = (ni & 1) ? bl[nj][1] : bl[nj][0];
                u32 l1 = (ni & 1) ? bl[nj][3] : bl[nj][2];
                mma16816(acc[mi][ni], ah[mi], h0, h1);
                mma16816(acc[mi][ni], al[mi], h0, h1);
                mma16816(acc[mi][ni], ah[mi], l0, l1);
            }
    }

    const int tq = lane >> 2, tr = lane & 3;
    #pragma unroll
    for (int mi = 0; mi < 2; ++mi)
        #pragma unroll
        for (int rh = 0; rh < 2; ++rh) {
            int m = bi + mw + mi * 16 + rh * 8 + tq;
            float sa = sqa[m];
            #pragma unroll
            for (int ni = 0; ni < 8; ++ni) {
                int n = bj + nw + ni * 8 + tr * 2;
                float v0 = fmaxf(sa + sqb[n]     - acc[mi][ni][rh * 2 + 0], 0.f);
                float v1 = fmaxf(sa + sqb[n + 1] - acc[mi][ni][rh * 2 + 1], 0.f);
                u32 q0 = __float_as_uint(fmaf(v0, inv, 8388608.0f));
                u32 q1 = __float_as_uint(fmaf(v1, inv, 8388608.0f));
                *(u32*)(Cq + (u64)m * Nn + n) = __byte_perm(q0, q1, 0x5410);
            }
        }
}

// ---------------- merged tile softmin + fused combine tail ----------------
// grid = NBLK + NCOMB. Blocks < NBLK do one tile each, then signal d_cnt.
// The last NCOMB blocks (issued last) spin until all tiles are done, run the
// combine/update, then handshake-reset both counters (replay-safe).
__global__ void __launch_bounds__(256, 3) tile_softmin_all_kernel(
    const uint4* __restrict__ Qxy, const uint4* __restrict__ Qxx, const uint4* __restrict__ Qyy,
    float* __restrict__ faa, float* __restrict__ gbb,
    float* __restrict__ gab, float* __restrict__ fba,
    float* __restrict__ tft, float* __restrict__ tgt,
    float* __restrict__ tftaa, float* __restrict__ tgtbb,
    const float* __restrict__ scales,
    const float* __restrict__ eps_ptr, float base_log, int init, int mode,
    float* __restrict__ pRM, float* __restrict__ pRS,
    float* __restrict__ pCM, float* __restrict__ pCS,
    float* __restrict__ pXM, float* __restrict__ pXS,
    float* __restrict__ pYM, float* __restrict__ pYS)
{
    const int tid = threadIdx.x;
    int b = blockIdx.x;

    if (b >= NBLK) {
        // ---- combine role ----
        if (tid == 0) {
            while (atomicAdd(&d_cnt, 0) < NBLK) __nanosleep(128);
        }
        __syncthreads();
        __threadfence();

        const int gid = (b - NBLK) * 256 + tid;   // 0..32767
        const int p = gid >> 13;
        const int i = gid & 8191;
        const float eps = *eps_ptr;
        const float sc = -eps * LN2;

        const float* pM = (p == 0) ? pRM : (p == 1) ? pCM : (p == 2) ? pXM : pYM;
        const float* pS = (p == 0) ? pRS : (p == 1) ? pCS : (p == 2) ? pXS : pYS;

        float M = -3.4e38f;
        #pragma unroll 16
        for (int c = 0; c < NCH; ++c) M = fmaxf(M, pM[(u64)c * Nn + i]);
        float S = 0.f;
        #pragma unroll 16
        for (int c = 0; c < NCH; ++c) S += pS[(u64)c * Nn + i] * ex2(pM[(u64)c * Nn + i] - M);
        float v = sc * (lg2(S) + M);

        float* dstA = (p == 0) ? fba : (p == 1) ? gab : (p == 2) ? faa : gbb;
        float* dstT = (p == 0) ? tft : (p == 1) ? tgt : (p == 2) ? tftaa : tgtbb;

        if (mode == 0)       dstA[i] = v;
        else if (mode == 1)  dstA[i] = 0.5f * (dstA[i] + v);
        else                 dstT[i] = v;

        // handshake-reset: last combine block past this point resets both counters
        __syncthreads();
        if (tid == 0) {
            __threadfence();
            if (atomicAdd(&d_cnt2, 1) == NCOMB - 1) {
                d_cnt2 = 0;
                __threadfence();
                d_cnt = 0;
            }
        }
        return;
    }

    // ---- tile role ----
    int which, bx, by;
    if (b < NCH * NCH) { which = 0; by = b >> 6; bx = b & 63; }
    else if (b < NCH * NCH + NTRI) { which = 1; sym_decode(b - NCH * NCH, by, bx); }
    else { which = 2; sym_decode(b - NCH * NCH - NTRI, by, bx); }

    const uint4* Q = (which == 0) ? Qxy : (which == 1) ? Qxx : Qyy;
    const float* potRow = (which == 0) ? gab : (which == 1) ? faa : gbb;
    const float* potCol = (which == 0) ? fba : (which == 1) ? faa : gbb;
    float* oRM = (which == 0) ? pRM : (which == 1) ? pXM : pYM;
    float* oRS = (which == 0) ? pRS : (which == 1) ? pXS : pYS;
    float* oCM = (which == 0) ? pCM : (which == 1) ? pXM : pYM;
    float* oCS = (which == 0) ? pCS : (which == 1) ? pXS : pYS;
    const bool doCol = (which == 0) || (by > bx);

    const int c16 = tid & 15, rp = tid >> 4;

    const float s2   = L2E / (*eps_ptr);
    const float b2   = base_log * L2E;
    const float scs2 = scales[which] * s2;
    const float off  = b2 + 8388608.0f * scs2;

    __shared__ float gp[128];
    __shared__ float fp[128];
    __shared__ float2 part[128 * 17];

    uint4 qv[8];
    #pragma unroll
    for (int p = 0; p < 8; ++p)
        qv[p] = __ldcs(&Q[(u64)(by * 128 + rp + 16 * p) * 1024 + bx * 16 + c16]);

    if (tid < 128) {
        float pv = init ? 0.f : potRow[bx * 128 + tid];
        gp[tid] = fmaf(pv, s2, off);
    } else {
        int t = tid - 128;
        float pv = init ? 0.f : potCol[by * 128 + t];
        fp[t] = fmaf(pv, s2, off);
    }
    __syncthreads();

    float4 gA = *(const float4*)&gp[c16 * 8];
    float4 gB = *(const float4*)&gp[c16 * 8 + 4];
    float fpv[8];
    #pragma unroll
    for (int p = 0; p < 8; ++p) fpv[p] = fp[rp + 16 * p];

    const float nscs2 = -scs2;

    #pragma unroll
    for (int p = 0; p < 8; ++p) {
        float v0 = fmaf(q2f_lo(qv[p].x), nscs2, gA.x);
        float v1 = fmaf(q2f_hi(qv[p].x), nscs2, gA.y);
        float v2 = fmaf(q2f_lo(qv[p].y), nscs2, gA.z);
        float v3 = fmaf(q2f_hi(qv[p].y), nscs2, gA.w);
        float v4 = fmaf(q2f_lo(qv[p].z), nscs2, gB.x);
        float v5 = fmaf(q2f_hi(qv[p].z), nscs2, gB.y);
        float v6 = fmaf(q2f_lo(qv[p].w), nscs2, gB.z);
        float v7 = fmaf(q2f_hi(qv[p].w), nscs2, gB.w);
        float m = fmaxf(fmaxf(fmaxf(v0, v1), fmaxf(v2, v3)),
                        fmaxf(fmaxf(v4, v5), fmaxf(v6, v7)));
        float s = ((ex2(v0 - m) + ex2(v1 - m)) + (ex2(v2 - m) + ex2(v3 - m)))
                + ((ex2(v4 - m) + ex2(v5 - m)) + (ex2(v6 - m) + ex2(v7 - m)));
        part[(rp + 16 * p) * 17 + c16] = make_float2(m, s);
    }
    __syncthreads();

    // ---- row merge: two-sweep ----
    if (tid < 128) {
        float M = -3.4e38f;
        #pragma unroll
        for (int k = 0; k < 16; ++k) M = fmaxf(M, part[tid * 17 + k].x);
        float S = 0.f;
        #pragma unroll
        for (int k = 0; k < 16; ++k) {
            float2 pk = part[tid * 17 + k];
            S += pk.y * ex2(pk.x - M);
        }
        u64 oidx = (u64)bx * Nn + by * 128 + tid;
        oRM[oidx] = M;
        oRS[oidx] = S;
    }

    if (doCol) {
        __syncthreads();
        #pragma unroll
        for (int e = 0; e < 8; ++e) {
            float v[8];
            #pragma unroll
            for (int p = 0; p < 8; ++p) {
                u32 a = (e < 2) ? qv[p].x : (e < 4) ? qv[p].y : (e < 6) ? qv[p].z : qv[p].w;
                float fq = (e & 1) ? q2f_hi(a) : q2f_lo(a);
                v[p] = fmaf(fq, nscs2, fpv[p]);
            }
            float m = fmaxf(fmaxf(fmaxf(v[0], v[1]), fmaxf(v[2], v[3])),
                            fmaxf(fmaxf(v[4], v[5]), fmaxf(v[6], v[7])));
            float s = ((ex2(v[0] - m) + ex2(v[1] - m)) + (ex2(v[2] - m) + ex2(v[3] - m)))
                    + ((ex2(v[4] - m) + ex2(v[5] - m)) + (ex2(v[6] - m) + ex2(v[7] - m)));
            part[(rp * 8 + e) * 17 + c16] = make_float2(m, s);
        }
        __syncthreads();
        // ---- col merge: two-sweep ----
        if (tid < 128) {
            int e = tid & 7, cc = tid >> 3;    // col = cc*8 + e
            float M = -3.4e38f;
            #pragma unroll
            for (int k = 0; k < 16; ++k) M = fmaxf(M, part[(k * 8 + e) * 17 + cc].x);
            float S = 0.f;
            #pragma unroll
            for (int k = 0; k < 16; ++k) {
                float2 pk = part[(k * 8 + e) * 17 + cc];
                S += pk.y * ex2(pk.x - M);
            }
            int col = cc * 8 + e;
            u64 oidx = (u64)by * Nn + bx * 128 + col;
            oCM[oidx] = M;
            oCS[oidx] = S;
        }
    }

    // ---- signal tile completion ----
    __syncthreads();
    if (tid == 0) {
        __threadfence();
        atomicAdd(&d_cnt, 1);
    }
}

// ---------------- final scalar ----------------
__global__ void final_kernel(const float* __restrict__ fbaf, const float* __restrict__ faaf,
                             const float* __restrict__ gabf, const float* __restrict__ gbbf,
                             float* __restrict__ out)
{
    __shared__ float red[32];
    int tid = threadIdx.x;
    int lane = tid & 31, wid = tid >> 5;
    float s = 0.f;
    for (int i = tid; i < Nn; i += 1024)
        s += (fbaf[i] - faaf[i]) + (gabf[i] - gbbf[i]);
    #pragma unroll
    for (int o = 16; o; o >>= 1) s += __shfl_xor_sync(0xffffffffu, s, o);
    if (lane == 0) red[wid] = s;
    __syncthreads();
    if (wid == 0) {
        float v = red[lane];
        #pragma unroll
        for (int o = 16; o; o >>= 1) v += __shfl_xor_sync(0xffffffffu, v, o);
        if (lane == 0) out[0] = v / (float)Nn;
    }
}

// ---------------- launch ----------------
extern "C" void kernel_launch(void* const* d_in, const int* in_sizes, int n_in,
                              void* d_out, int out_size)
{
    const float* X   = (const float*)d_in[0];
    const float* Y   = (const float*)d_in[1];
    const float* eps = (const float*)d_in[2];
    const int n_eps  = in_sizes[2];
    float* out = (float*)d_out;

    u16 *Cxy, *Cxx, *Cyy;
    __nv_bfloat16 *Xh, *Xl, *Yh, *Yl;
    float *sqx, *sqy, *scales;
    float *faa, *gbb, *gab, *fba, *tft, *tgt, *tftaa, *tgtbb;
    float *pRM, *pRS, *pCM, *pCS, *pXM, *pXS, *pYM, *pYS;
    cudaGetSymbolAddress((void**)&Cxy, d_Cxy);
    cudaGetSymbolAddress((void**)&Cxx, d_Cxx);
    cudaGetSymbolAddress((void**)&Cyy, d_Cyy);
    cudaGetSymbolAddress((void**)&Xh, d_Xh);
    cudaGetSymbolAddress((void**)&Xl, d_Xl);
    cudaGetSymbolAddress((void**)&Yh, d_Yh);
    cudaGetSymbolAddress((void**)&Yl, d_Yl);
    cudaGetSymbolAddress((void**)&sqx, d_sqx);
    cudaGetSymbolAddress((void**)&sqy, d_sqy);
    cudaGetSymbolAddress((void**)&scales, d_scales);
    cudaGetSymbolAddress((void**)&faa, d_faa);
    cudaGetSymbolAddress((void**)&gbb, d_gbb);
    cudaGetSymbolAddress((void**)&gab, d_gab);
    cudaGetSymbolAddress((void**)&fba, d_fba);
    cudaGetSymbolAddress((void**)&tft, d_tft);
    cudaGetSymbolAddress((void**)&tgt, d_tgt);
    cudaGetSymbolAddress((void**)&tftaa, d_tftaa);
    cudaGetSymbolAddress((void**)&tgtbb, d_tgtbb);
    cudaGetSymbolAddress((void**)&pRM, d_pRM);
    cudaGetSymbolAddress((void**)&pRS, d_pRS);
    cudaGetSymbolAddress((void**)&pCM, d_pCM);
    cudaGetSymbolAddress((void**)&pCS, d_pCS);
    cudaGetSymbolAddress((void**)&pXM, d_pXM);
    cudaGetSymbolAddress((void**)&pXS, d_pXS);
    cudaGetSymbolAddress((void**)&pYM, d_pYM);
    cudaGetSymbolAddress((void**)&pYS, d_pYS);

    cudaFuncSetAttribute(mma_gemm_all_kernel,
                         cudaFuncAttributeMaxDynamicSharedMemorySize, 65536);

    const float LOGW = -logf((float)Nn);

    prep_kernel<<<2048, 256>>>(X, Y, sqx, sqy, Xh, Xl, Yh, Yl);
    scale_kernel<<<1, 256>>>(sqx, sqy, scales);
    mma_gemm_all_kernel<<<NBLK, 256, 65536>>>(Xh, Xl, Yh, Yl, sqx, sqy, scales,
                                              Cxy, Cxx, Cyy);

    for (int k = -1; k <= n_eps; ++k) {
        const float* ek = (k < 0) ? eps : (k < n_eps ? eps + k : eps + (n_eps - 1));
        int mode = (k < 0) ? 0 : (k < n_eps ? 1 : 2);
        int init = (k < 0) ? 1 : 0;
        tile_softmin_all_kernel<<<NBLK + NCOMB, 256>>>(
            (const uint4*)Cxy, (const uint4*)Cxx, (const uint4*)Cyy,
            faa, gbb, gab, fba, tft, tgt, tftaa, tgtbb,
            scales, ek, LOGW, init, mode,
            pRM, pRS, pCM, pCS, pXM, pXS, pYM, pYS);
    }

    final_kernel<<<1, 1024>>>(tft, tftaa, tgt, tgtbb, out);
}

// round 16
// speedup vs baseline: 1.0479x; 1.0479x over previous
#include <cuda_runtime.h>
#include <cuda_bf16.h>
#include <math.h>
#include <stdint.h>

typedef unsigned long long u64;
typedef unsigned int u32;
typedef unsigned short u16;

#define Nn 8192
#define NCH 64
#define NTRI (NCH * (NCH + 1) / 2)
#define NOFF (NCH * (NCH - 1) / 2)      // 2016 strictly-lower tiles
#define NBLK (NCH * NCH + 2 * NTRI)     // 8256 tiles
#define L2E 1.44269504088896f
#define LN2 0.69314718055995f

// ---------------- static scratch ----------------
__device__ u16 d_Cxy[(u64)Nn * Nn];
__device__ u16 d_Cxx[(u64)Nn * Nn];
__device__ u16 d_Cyy[(u64)Nn * Nn];
__device__ __nv_bfloat16 d_Xh[(u64)Nn * 64], d_Xl[(u64)Nn * 64];
__device__ __nv_bfloat16 d_Yh[(u64)Nn * 64], d_Yl[(u64)Nn * 64];
__device__ float d_sqx[Nn], d_sqy[Nn];
__device__ float d_scales[6];
__device__ float d_faa[Nn], d_gbb[Nn], d_gab[Nn], d_fba[Nn];
__device__ float d_tft[Nn], d_tgt[Nn], d_tftaa[Nn], d_tgtbb[Nn];
__device__ float d_pRM[(u64)NCH * Nn], d_pRS[(u64)NCH * Nn];
__device__ float d_pCM[(u64)NCH * Nn], d_pCS[(u64)NCH * Nn];
__device__ float d_pXM[(u64)NCH * Nn], d_pXS[(u64)NCH * Nn];
__device__ float d_pYM[(u64)NCH * Nn], d_pYS[(u64)NCH * Nn];

__device__ __forceinline__ float ex2(float x) {
    float r; asm("ex2.approx.ftz.f32 %0, %1;" : "=f"(r) : "f"(x)); return r;
}
__device__ __forceinline__ float lg2(float x) {
    float r; asm("lg2.approx.f32 %0, %1;" : "=f"(r) : "f"(x)); return r;
}
// strictly-lower tiles first (i < NOFF), diagonals last
__device__ __forceinline__ void sym_decode(int i, int& by, int& bx) {
    if (i < NOFF) {
        int r = (int)((1.0f + sqrtf(1.0f + 8.0f * (float)i)) * 0.5f);
        while ((r + 1) * r / 2 <= i) ++r;
        while (r * (r - 1) / 2 > i) --r;
        by = r; bx = i - r * (r - 1) / 2;
    } else {
        by = bx = i - NOFF;
    }
}
__device__ __forceinline__ float q2f_lo(u32 a) {
    return __uint_as_float(__byte_perm(a, 0x4B000000u, 0x7410));
}
__device__ __forceinline__ float q2f_hi(u32 a) {
    return __uint_as_float(__byte_perm(a, 0x4B000000u, 0x7432));
}
__device__ __forceinline__ void ldsm4(u32& r0, u32& r1, u32& r2, u32& r3, u32 addr) {
    asm volatile("ldmatrix.sync.aligned.m8n8.x4.shared.b16 {%0,%1,%2,%3}, [%4];"
                 : "=r"(r0), "=r"(r1), "=r"(r2), "=r"(r3) : "r"(addr));
}
__device__ __forceinline__ void mma16816(float* d, const u32* a, u32 b0, u32 b1) {
    asm volatile(
        "mma.sync.aligned.m16n8k16.row.col.f32.bf16.bf16.f32 "
        "{%0,%1,%2,%3}, {%4,%5,%6,%7}, {%8,%9}, {%0,%1,%2,%3};"
        : "+f"(d[0]), "+f"(d[1]), "+f"(d[2]), "+f"(d[3])
        : "r"(a[0]), "r"(a[1]), "r"(a[2]), "r"(a[3]), "r"(b0), "r"(b1));
}

// ---------------- prep: sqnorm + bf16 hi/lo split for X and Y ----------------
__global__ void prep_kernel(const float* __restrict__ X, const float* __restrict__ Y,
                            float* __restrict__ sqx, float* __restrict__ sqy,
                            __nv_bfloat16* __restrict__ Xh, __nv_bfloat16* __restrict__ Xl,
                            __nv_bfloat16* __restrict__ Yh, __nv_bfloat16* __restrict__ Yl)
{
    int gw   = (blockIdx.x * blockDim.x + threadIdx.x) >> 5;
    int lane = threadIdx.x & 31;
    int row  = gw & 8191;
    const float* src = (gw < 8192) ? X : Y;
    float* sq = (gw < 8192) ? sqx : sqy;
    __nv_bfloat16* hi = (gw < 8192) ? Xh : Yh;
    __nv_bfloat16* lo = (gw < 8192) ? Xl : Yl;

    float a = src[(u64)row * 64 + lane];
    float b = src[(u64)row * 64 + lane + 32];
    __nv_bfloat16 ha = __float2bfloat16(a), hb = __float2bfloat16(b);
    hi[(u64)row * 64 + lane]      = ha;
    hi[(u64)row * 64 + lane + 32] = hb;
    lo[(u64)row * 64 + lane]      = __float2bfloat16(a - __bfloat162float(ha));
    lo[(u64)row * 64 + lane + 32] = __float2bfloat16(b - __bfloat162float(hb));
    float s = a * a + b * b;
    #pragma unroll
    for (int o = 16; o; o >>= 1) s += __shfl_xor_sync(0xffffffffu, s, o);
    if (lane == 0) sq[row] = 0.5f * s;
}

// ---------------- global quantization scales ----------------
__global__ void scale_kernel(const float* __restrict__ sqx, const float* __restrict__ sqy,
                             float* __restrict__ scales) {
    __shared__ float red[16];
    int tid = threadIdx.x, lane = tid & 31, w = tid >> 5;
    float mx = 0.f, my = 0.f;
    for (int i = tid; i < Nn; i += 256) {
        mx = fmaxf(mx, sqx[i]);
        my = fmaxf(my, sqy[i]);
    }
    #pragma unroll
    for (int o = 16; o; o >>= 1) {
        mx = fmaxf(mx, __shfl_xor_sync(0xffffffffu, mx, o));
        my = fmaxf(my, __shfl_xor_sync(0xffffffffu, my, o));
    }
    if (lane == 0) { red[w] = mx; red[w + 8] = my; }
    __syncthreads();
    if (tid == 0) {
        float MX = red[0], MY = red[8];
        #pragma unroll
        for (int i = 1; i < 8; ++i) { MX = fmaxf(MX, red[i]); MY = fmaxf(MY, red[8 + i]); }
        float cxy = MX + MY + 2.0f * sqrtf(MX * MY);
        scales[0] = cxy / 65500.0f;       scales[3] = 65500.0f / cxy;
        scales[1] = 4.0f * MX / 65500.0f; scales[4] = 65500.0f / (4.0f * MX);
        scales[2] = 4.0f * MY / 65500.0f; scales[5] = 65500.0f / (4.0f * MY);
    }
}

// ---------------- merged tensor-core cost GEMM (all three matrices, one launch) -----
__global__ void __launch_bounds__(256, 2) mma_gemm_all_kernel(
    const __nv_bfloat16* __restrict__ Xh, const __nv_bfloat16* __restrict__ Xl,
    const __nv_bfloat16* __restrict__ Yh, const __nv_bfloat16* __restrict__ Yl,
    const float* __restrict__ sqx, const float* __restrict__ sqy,
    const float* __restrict__ scales,
    u16* __restrict__ Cxy, u16* __restrict__ Cxx, u16* __restrict__ Cyy)
{
    int b = blockIdx.x;
    int which, bxi, byi;
    if (b < NCH * NCH) { which = 0; byi = b >> 6; bxi = b & 63; }
    else if (b < NCH * NCH + NTRI) { which = 1; sym_decode(b - NCH * NCH, byi, bxi); }
    else { which = 2; sym_decode(b - NCH * NCH - NTRI, byi, bxi); }

    const __nv_bfloat16* Ah_g = (which == 2) ? Yh : Xh;
    const __nv_bfloat16* Al_g = (which == 2) ? Yl : Xl;
    const __nv_bfloat16* Bh_g = (which == 1) ? Xh : Yh;
    const __nv_bfloat16* Bl_g = (which == 1) ? Xl : Yl;
    const float* sqa = (which == 2) ? sqy : sqx;
    const float* sqb = (which == 1) ? sqx : sqy;
    const float inv = scales[3 + which];
    u16* Cq = (which == 0) ? Cxy : (which == 1) ? Cxx : Cyy;

    const int bi = byi * 128, bj = bxi * 128;
    extern __shared__ __nv_bfloat16 sh[];
    __nv_bfloat16* sAh = sh;
    __nv_bfloat16* sAl = sh + 8192;
    __nv_bfloat16* sBh = sh + 16384;
    __nv_bfloat16* sBl = sh + 24576;
    const int tid = threadIdx.x;

    #pragma unroll
    for (int i = 0; i < 4; ++i) {
        int idx = tid + i * 256;
        int r = idx >> 3, c = idx & 7;
        int sc = c ^ (r & 7);
        ((uint4*)sAh)[r * 8 + sc] = *(const uint4*)(Ah_g + (u64)(bi + r) * 64 + c * 8);
        ((uint4*)sAl)[r * 8 + sc] = *(const uint4*)(Al_g + (u64)(bi + r) * 64 + c * 8);
        ((uint4*)sBh)[r * 8 + sc] = *(const uint4*)(Bh_g + (u64)(bj + r) * 64 + c * 8);
        ((uint4*)sBl)[r * 8 + sc] = *(const uint4*)(Bl_g + (u64)(bj + r) * 64 + c * 8);
    }
    __syncthreads();

    const int w = tid >> 5, lane = tid & 31;
    const int mw = (w & 3) * 32, nw = (w >> 2) * 64;
    const int lq = lane >> 3, lr = lane & 7;
    const u32 baseAh = (u32)__cvta_generic_to_shared(sAh);
    const u32 baseAl = (u32)__cvta_generic_to_shared(sAl);
    const u32 baseBh = (u32)__cvta_generic_to_shared(sBh);
    const u32 baseBl = (u32)__cvta_generic_to_shared(sBl);

    float acc[2][8][4];
    #pragma unroll
    for (int mi = 0; mi < 2; ++mi)
        #pragma unroll
        for (int ni = 0; ni < 8; ++ni)
            #pragma unroll
            for (int e = 0; e < 4; ++e) acc[mi][ni][e] = 0.f;

    #pragma unroll
    for (int ks = 0; ks < 4; ++ks) {
        const int ch = ks * 2 + (lq >> 1);
        u32 ah[2][4], al[2][4];
        #pragma unroll
        for (int mi = 0; mi < 2; ++mi) {
            int row = mw + mi * 16 + (lq & 1) * 8 + lr;
            u32 off = (u32)(row * 128 + ((ch ^ (row & 7)) << 4));
            ldsm4(ah[mi][0], ah[mi][1], ah[mi][2], ah[mi][3], baseAh + off);
            ldsm4(al[mi][0], al[mi][1], al[mi][2], al[mi][3], baseAl + off);
        }
        u32 bh[4][4], bl[4][4];
        #pragma unroll
        for (int nj = 0; nj < 4; ++nj) {
            int row = nw + nj * 16 + (lq & 1) * 8 + lr;
            u32 off = (u32)(row * 128 + ((ch ^ (row & 7)) << 4));
            ldsm4(bh[nj][0], bh[nj][1], bh[nj][2], bh[nj][3], baseBh + off);
            ldsm4(bl[nj][0], bl[nj][1], bl[nj][2], bl[nj][3], baseBl + off);
        }
        #pragma unroll
        for (int mi = 0; mi < 2; ++mi)
            #pragma unroll
            for (int ni = 0; ni < 8; ++ni) {
                int nj = ni >> 1;
                u32 h0 = (ni & 1) ? bh[nj][1] : bh[nj][0];
                u32 h1 = (ni & 1) ? bh[nj][3] : bh[nj][2];
                u32 l0 = (ni & 1) ? bl[nj][1] : bl[nj][0];
                u32 l1 = (ni & 1) ? bl[nj][3] : bl[nj][2];
                mma16816(acc[mi][ni], ah[mi], h0, h1);
                mma16816(acc[mi][ni], al[mi], h0, h1);
                mma16816(acc[mi][ni], ah[mi], l0, l1);
            }
    }

    const int tq = lane >> 2, tr = lane & 3;
    #pragma unroll
    for (int mi = 0; mi < 2; ++mi)
        #pragma unroll
        for (int rh = 0; rh < 2; ++rh) {
            int m = bi + mw + mi * 16 + rh * 8 + tq;
            float sa = sqa[m];
            #pragma unroll
            for (int ni = 0; ni < 8; ++ni) {
                int n = bj + nw + ni * 8 + tr * 2;
                float v0 = fmaxf(sa + sqb[n]     - acc[mi][ni][rh * 2 + 0], 0.f);
                float v1 = fmaxf(sa + sqb[n + 1] - acc[mi][ni][rh * 2 + 1], 0.f);
                u32 q0 = __float_as_uint(fmaf(v0, inv, 8388608.0f));
                u32 q1 = __float_as_uint(fmaf(v1, inv, 8388608.0f));
                *(u32*)(Cq + (u64)m * Nn + n) = __byte_perm(q0, q1, 0x5410);
            }
        }
}

// ---------------- merged tile softmin: all three matrices, 3 CTAs/SM ----------------
__global__ void __launch_bounds__(256, 3) tile_softmin_all_kernel(
    const uint4* __restrict__ Qxy, const uint4* __restrict__ Qxx, const uint4* __restrict__ Qyy,
    const float* __restrict__ faa, const float* __restrict__ gbb,
    const float* __restrict__ gab, const float* __restrict__ fba,
    const float* __restrict__ scales,
    const float* __restrict__ eps_ptr, float base_log, int init,
    float* __restrict__ pRM, float* __restrict__ pRS,
    float* __restrict__ pCM, float* __restrict__ pCS,
    float* __restrict__ pXM, float* __restrict__ pXS,
    float* __restrict__ pYM, float* __restrict__ pYS)
{
    int b = blockIdx.x;
    int which, bx, by;
    if (b < NCH * NCH) { which = 0; by = b >> 6; bx = b & 63; }
    else if (b < NCH * NCH + NTRI) { which = 1; sym_decode(b - NCH * NCH, by, bx); }
    else { which = 2; sym_decode(b - NCH * NCH - NTRI, by, bx); }

    const uint4* Q = (which == 0) ? Qxy : (which == 1) ? Qxx : Qyy;
    const float* potRow = (which == 0) ? gab : (which == 1) ? faa : gbb;
    const float* potCol = (which == 0) ? fba : (which == 1) ? faa : gbb;
    float* oRM = (which == 0) ? pRM : (which == 1) ? pXM : pYM;
    float* oRS = (which == 0) ? pRS : (which == 1) ? pXS : pYS;
    float* oCM = (which == 0) ? pCM : (which == 1) ? pXM : pYM;
    float* oCS = (which == 0) ? pCS : (which == 1) ? pXS : pYS;
    const bool doCol = (which == 0) || (by > bx);

    const int tid = threadIdx.x;
    const int c16 = tid & 15, rp = tid >> 4;

    const float s2   = L2E / (*eps_ptr);
    const float b2   = base_log * L2E;
    const float scs2 = scales[which] * s2;
    const float off  = b2 + 8388608.0f * scs2;

    __shared__ float gp[128];
    __shared__ float fp[128];
    __shared__ float2 part[128 * 17];

    uint4 qv[8];
    #pragma unroll
    for (int p = 0; p < 8; ++p)
        qv[p] = __ldcs(&Q[(u64)(by * 128 + rp + 16 * p) * 1024 + bx * 16 + c16]);

    if (tid < 128) {
        float pv = init ? 0.f : potRow[bx * 128 + tid];
        gp[tid] = fmaf(pv, s2, off);
    } else {
        int t = tid - 128;
        float pv = init ? 0.f : potCol[by * 128 + t];
        fp[t] = fmaf(pv, s2, off);
    }
    __syncthreads();

    float4 gA = *(const float4*)&gp[c16 * 8];
    float4 gB = *(const float4*)&gp[c16 * 8 + 4];
    float fpv[8];
    #pragma unroll
    for (int p = 0; p < 8; ++p) fpv[p] = fp[rp + 16 * p];

    const float nscs2 = -scs2;

    #pragma unroll
    for (int p = 0; p < 8; ++p) {
        float v0 = fmaf(q2f_lo(qv[p].x), nscs2, gA.x);
        float v1 = fmaf(q2f_hi(qv[p].x), nscs2, gA.y);
        float v2 = fmaf(q2f_lo(qv[p].y), nscs2, gA.z);
        float v3 = fmaf(q2f_hi(qv[p].y), nscs2, gA.w);
        float v4 = fmaf(q2f_lo(qv[p].z), nscs2, gB.x);
        float v5 = fmaf(q2f_hi(qv[p].z), nscs2, gB.y);
        float v6 = fmaf(q2f_lo(qv[p].w), nscs2, gB.z);
        float v7 = fmaf(q2f_hi(qv[p].w), nscs2, gB.w);
        float m = fmaxf(fmaxf(fmaxf(v0, v1), fmaxf(v2, v3)),
                        fmaxf(fmaxf(v4, v5), fmaxf(v6, v7)));
        float s = ((ex2(v0 - m) + ex2(v1 - m)) + (ex2(v2 - m) + ex2(v3 - m)))
                + ((ex2(v4 - m) + ex2(v5 - m)) + (ex2(v6 - m) + ex2(v7 - m)));
        part[(rp + 16 * p) * 17 + c16] = make_float2(m, s);
    }
    __syncthreads();

    // ---- row merge: two-sweep (max sweep, then rescaled-sum sweep) ----
    if (tid < 128) {
        float M = -3.4e38f;
        #pragma unroll
        for (int k = 0; k < 16; ++k) M = fmaxf(M, part[tid * 17 + k].x);
        float S = 0.f;
        #pragma unroll
        for (int k = 0; k < 16; ++k) {
            float2 pk = part[tid * 17 + k];
            S += pk.y * ex2(pk.x - M);
        }
        u64 oidx = (u64)bx * Nn + by * 128 + tid;
        oRM[oidx] = M;
        oRS[oidx] = S;
    }

    if (doCol) {
        __syncthreads();
        #pragma unroll
        for (int e = 0; e < 8; ++e) {
            float v[8];
            #pragma unroll
            for (int p = 0; p < 8; ++p) {
                u32 a = (e < 2) ? qv[p].x : (e < 4) ? qv[p].y : (e < 6) ? qv[p].z : qv[p].w;
                float fq = (e & 1) ? q2f_hi(a) : q2f_lo(a);
                v[p] = fmaf(fq, nscs2, fpv[p]);
            }
            float m = fmaxf(fmaxf(fmaxf(v[0], v[1]), fmaxf(v[2], v[3])),
                            fmaxf(fmaxf(v[4], v[5]), fmaxf(v[6], v[7])));
            float s = ((ex2(v[0] - m) + ex2(v[1] - m)) + (ex2(v[2] - m) + ex2(v[3] - m)))
                    + ((ex2(v[4] - m) + ex2(v[5] - m)) + (ex2(v[6] - m) + ex2(v[7] - m)));
            part[(rp * 8 + e) * 17 + c16] = make_float2(m, s);
        }
        __syncthreads();
        // ---- col merge: two-sweep ----
        if (tid < 128) {
            int e = tid & 7, cc = tid >> 3;    // col = cc*8 + e
            float M = -3.4e38f;
            #pragma unroll
            for (int k = 0; k < 16; ++k) M = fmaxf(M, part[(k * 8 + e) * 17 + cc].x);
            float S = 0.f;
            #pragma unroll
            for (int k = 0; k < 16; ++k) {
                float2 pk = part[(k * 8 + e) * 17 + cc];
                S += pk.y * ex2(pk.x - M);
            }
            int col = cc * 8 + e;
            u64 oidx = (u64)by * Nn + bx * 128 + col;
            oCM[oidx] = M;
            oCS[oidx] = S;
        }
    }
}

// ---------------- combine: one output per thread, 32768 threads ----------------
__global__ void __launch_bounds__(256) combine_update_kernel(
    const float* __restrict__ pRM, const float* __restrict__ pRS,
    const float* __restrict__ pCM, const float* __restrict__ pCS,
    const float* __restrict__ pXM, const float* __restrict__ pXS,
    const float* __restrict__ pYM, const float* __restrict__ pYS,
    const float* __restrict__ eps_ptr, int mode,
    float* __restrict__ faa, float* __restrict__ gbb,
    float* __restrict__ gab, float* __restrict__ fba,
    float* __restrict__ tft, float* __restrict__ tgt,
    float* __restrict__ tftaa, float* __restrict__ tgtbb)
{
    const int gid = blockIdx.x * 256 + threadIdx.x;   // 0..32767
    const int p = gid >> 13;
    const int i = gid & 8191;
    const float eps = *eps_ptr;
    const float sc = -eps * LN2;

    const float* pM = (p == 0) ? pRM : (p == 1) ? pCM : (p == 2) ? pXM : pYM;
    const float* pS = (p == 0) ? pRS : (p == 1) ? pCS : (p == 2) ? pXS : pYS;

    float M = -3.4e38f;
    #pragma unroll 16
    for (int c = 0; c < NCH; ++c) M = fmaxf(M, pM[(u64)c * Nn + i]);
    float S = 0.f;
    #pragma unroll 16
    for (int c = 0; c < NCH; ++c) S += pS[(u64)c * Nn + i] * ex2(pM[(u64)c * Nn + i] - M);
    float v = sc * (lg2(S) + M);

    float* dstA = (p == 0) ? fba : (p == 1) ? gab : (p == 2) ? faa : gbb;
    float* dstT = (p == 0) ? tft : (p == 1) ? tgt : (p == 2) ? tftaa : tgtbb;

    if (mode == 0)       dstA[i] = v;
    else if (mode == 1)  dstA[i] = 0.5f * (dstA[i] + v);
    else                 dstT[i] = v;
}

// ---------------- final scalar ----------------
__global__ void final_kernel(const float* __restrict__ fbaf, const float* __restrict__ faaf,
                             const float* __restrict__ gabf, const float* __restrict__ gbbf,
                             float* __restrict__ out)
{
    __shared__ float red[32];
    int tid = threadIdx.x;
    int lane = tid & 31, wid = tid >> 5;
    float s = 0.f;
    for (int i = tid; i < Nn; i += 1024)
        s += (fbaf[i] - faaf[i]) + (gabf[i] - gbbf[i]);
    #pragma unroll
    for (int o = 16; o; o >>= 1) s += __shfl_xor_sync(0xffffffffu, s, o);
    if (lane == 0) red[wid] = s;
    __syncthreads();
    if (wid == 0) {
        float v = red[lane];
        #pragma unroll
        for (int o = 16; o; o >>= 1) v += __shfl_xor_sync(0xffffffffu, v, o);
        if (lane == 0) out[0] = v / (float)Nn;
    }
}

// ---------------- launch ----------------
extern "C" void kernel_launch(void* const* d_in, const int* in_sizes, int n_in,
                              void* d_out, int out_size)
{
    const float* X   = (const float*)d_in[0];
    const float* Y   = (const float*)d_in[1];
    const float* eps = (const float*)d_in[2];
    const int n_eps  = in_sizes[2];
    float* out = (float*)d_out;

    u16 *Cxy, *Cxx, *Cyy;
    __nv_bfloat16 *Xh, *Xl, *Yh, *Yl;
    float *sqx, *sqy, *scales;
    float *faa, *gbb, *gab, *fba, *tft, *tgt, *tftaa, *tgtbb;
    float *pRM, *pRS, *pCM, *pCS, *pXM, *pXS, *pYM, *pYS;
    cudaGetSymbolAddress((void**)&Cxy, d_Cxy);
    cudaGetSymbolAddress((void**)&Cxx, d_Cxx);
    cudaGetSymbolAddress((void**)&Cyy, d_Cyy);
    cudaGetSymbolAddress((void**)&Xh, d_Xh);
    cudaGetSymbolAddress((void**)&Xl, d_Xl);
    cudaGetSymbolAddress((void**)&Yh, d_Yh);
    cudaGetSymbolAddress((void**)&Yl, d_Yl);
    cudaGetSymbolAddress((void**)&sqx, d_sqx);
    cudaGetSymbolAddress((void**)&sqy, d_sqy);
    cudaGetSymbolAddress((void**)&scales, d_scales);
    cudaGetSymbolAddress((void**)&faa, d_faa);
    cudaGetSymbolAddress((void**)&gbb, d_gbb);
    cudaGetSymbolAddress((void**)&gab, d_gab);
    cudaGetSymbolAddress((void**)&fba, d_fba);
    cudaGetSymbolAddress((void**)&tft, d_tft);
    cudaGetSymbolAddress((void**)&tgt, d_tgt);
    cudaGetSymbolAddress((void**)&tftaa, d_tftaa);
    cudaGetSymbolAddress((void**)&tgtbb, d_tgtbb);
    cudaGetSymbolAddress((void**)&pRM, d_pRM);
    cudaGetSymbolAddress((void**)&pRS, d_pRS);
    cudaGetSymbolAddress((void**)&pCM, d_pCM);
    cudaGetSymbolAddress((void**)&pCS, d_pCS);
    cudaGetSymbolAddress((void**)&pXM, d_pXM);
    cudaGetSymbolAddress((void**)&pXS, d_pXS);
    cudaGetSymbolAddress((void**)&pYM, d_pYM);
    cudaGetSymbolAddress((void**)&pYS, d_pYS);

    cudaFuncSetAttribute(mma_gemm_all_kernel,
                         cudaFuncAttributeMaxDynamicSharedMemorySize, 65536);

    const float LOGW = -logf((float)Nn);

    prep_kernel<<<2048, 256>>>(X, Y, sqx, sqy, Xh, Xl, Yh, Yl);
    scale_kernel<<<1, 256>>>(sqx, sqy, scales);
    mma_gemm_all_kernel<<<NBLK, 256, 65536>>>(Xh, Xl, Yh, Yl, sqx, sqy, scales,
                                              Cxy, Cxx, Cyy);

    for (int k = -1; k <= n_eps; ++k) {
        const float* ek = (k < 0) ? eps : (k < n_eps ? eps + k : eps + (n_eps - 1));
        int mode = (k < 0) ? 0 : (k < n_eps ? 1 : 2);
        int init = (k < 0) ? 1 : 0;
        tile_softmin_all_kernel<<<NBLK, 256>>>(
            (const uint4*)Cxy, (const uint4*)Cxx, (const uint4*)Cyy,
            faa, gbb, gab, fba, scales, ek, LOGW, init,
            pRM, pRS, pCM, pCS, pXM, pXS, pYM, pYS);
        combine_update_kernel<<<128, 256>>>(
            pRM, pRS, pCM, pCS, pXM, pXS, pYM, pYS, ek, mode,
            faa, gbb, gab, fba, tft, tgt, tftaa, tgtbb);
    }

    final_kernel<<<1, 1024>>>(tft, tftaa, tgt, tgtbb, out);
}

// round 17
// speedup vs baseline: 1.0739x; 1.0248x over previous
#include <cuda_runtime.h>
#include <cuda_bf16.h>
#include <math.h>
#include <stdint.h>

typedef unsigned long long u64;
typedef unsigned int u32;
typedef unsigned short u16;

#define Nn 8192
#define NCH 64
#define NTRI (NCH * (NCH + 1) / 2)
#define NOFF (NCH * (NCH - 1) / 2)      // 2016 strictly-lower tiles
#define NBLK (NCH * NCH + 2 * NTRI)     // 8256 tiles
#define L2E 1.44269504088896f
#define LN2 0.69314718055995f

// ---------------- static scratch ----------------
__device__ u16 d_Cxy[(u64)Nn * Nn];
__device__ u16 d_Cxx[(u64)Nn * Nn];
__device__ u16 d_Cyy[(u64)Nn * Nn];
__device__ __nv_bfloat16 d_Xh[(u64)Nn * 64], d_Xl[(u64)Nn * 64];
__device__ __nv_bfloat16 d_Yh[(u64)Nn * 64], d_Yl[(u64)Nn * 64];
__device__ float d_sqx[Nn], d_sqy[Nn];
__device__ float d_scales[6];
__device__ float d_faa[Nn], d_gbb[Nn], d_gab[Nn], d_fba[Nn];
__device__ float d_tft[Nn], d_tgt[Nn], d_tftaa[Nn], d_tgtbb[Nn];
__device__ float d_pR[(u64)NCH * Nn];   // single-float LSE partials (M + lg2 S)
__device__ float d_pC[(u64)NCH * Nn];
__device__ float d_pX[(u64)NCH * Nn];
__device__ float d_pY[(u64)NCH * Nn];

__device__ __forceinline__ float ex2(float x) {
    float r; asm("ex2.approx.ftz.f32 %0, %1;" : "=f"(r) : "f"(x)); return r;
}
__device__ __forceinline__ float lg2(float x) {
    float r; asm("lg2.approx.f32 %0, %1;" : "=f"(r) : "f"(x)); return r;
}
// strictly-lower tiles first (i < NOFF), diagonals last
__device__ __forceinline__ void sym_decode(int i, int& by, int& bx) {
    if (i < NOFF) {
        int r = (int)((1.0f + sqrtf(1.0f + 8.0f * (float)i)) * 0.5f);
        while ((r + 1) * r / 2 <= i) ++r;
        while (r * (r - 1) / 2 > i) --r;
        by = r; bx = i - r * (r - 1) / 2;
    } else {
        by = bx = i - NOFF;
    }
}
__device__ __forceinline__ float q2f_lo(u32 a) {
    return __uint_as_float(__byte_perm(a, 0x4B000000u, 0x7410));
}
__device__ __forceinline__ float q2f_hi(u32 a) {
    return __uint_as_float(__byte_perm(a, 0x4B000000u, 0x7432));
}
__device__ __forceinline__ void ldsm4(u32& r0, u32& r1, u32& r2, u32& r3, u32 addr) {
    asm volatile("ldmatrix.sync.aligned.m8n8.x4.shared.b16 {%0,%1,%2,%3}, [%4];"
                 : "=r"(r0), "=r"(r1), "=r"(r2), "=r"(r3) : "r"(addr));
}
__device__ __forceinline__ void mma16816(float* d, const u32* a, u32 b0, u32 b1) {
    asm volatile(
        "mma.sync.aligned.m16n8k16.row.col.f32.bf16.bf16.f32 "
        "{%0,%1,%2,%3}, {%4,%5,%6,%7}, {%8,%9}, {%0,%1,%2,%3};"
        : "+f"(d[0]), "+f"(d[1]), "+f"(d[2]), "+f"(d[3])
        : "r"(a[0]), "r"(a[1]), "r"(a[2]), "r"(a[3]), "r"(b0), "r"(b1));
}

// ---------------- prep: sqnorm + bf16 hi/lo split for X and Y ----------------
__global__ void prep_kernel(const float* __restrict__ X, const float* __restrict__ Y,
                            float* __restrict__ sqx, float* __restrict__ sqy,
                            __nv_bfloat16* __restrict__ Xh, __nv_bfloat16* __restrict__ Xl,
                            __nv_bfloat16* __restrict__ Yh, __nv_bfloat16* __restrict__ Yl)
{
    int gw   = (blockIdx.x * blockDim.x + threadIdx.x) >> 5;
    int lane = threadIdx.x & 31;
    int row  = gw & 8191;
    const float* src = (gw < 8192) ? X : Y;
    float* sq = (gw < 8192) ? sqx : sqy;
    __nv_bfloat16* hi = (gw < 8192) ? Xh : Yh;
    __nv_bfloat16* lo = (gw < 8192) ? Xl : Yl;

    float a = src[(u64)row * 64 + lane];
    float b = src[(u64)row * 64 + lane + 32];
    __nv_bfloat16 ha = __float2bfloat16(a), hb = __float2bfloat16(b);
    hi[(u64)row * 64 + lane]      = ha;
    hi[(u64)row * 64 + lane + 32] = hb;
    lo[(u64)row * 64 + lane]      = __float2bfloat16(a - __bfloat162float(ha));
    lo[(u64)row * 64 + lane + 32] = __float2bfloat16(b - __bfloat162float(hb));
    float s = a * a + b * b;
    #pragma unroll
    for (int o = 16; o; o >>= 1) s += __shfl_xor_sync(0xffffffffu, s, o);
    if (lane == 0) sq[row] = 0.5f * s;
}

// ---------------- global quantization scales ----------------
__global__ void scale_kernel(const float* __restrict__ sqx, const float* __restrict__ sqy,
                             float* __restrict__ scales) {
    __shared__ float red[16];
    int tid = threadIdx.x, lane = tid & 31, w = tid >> 5;
    float mx = 0.f, my = 0.f;
    for (int i = tid; i < Nn; i += 256) {
        mx = fmaxf(mx, sqx[i]);
        my = fmaxf(my, sqy[i]);
    }
    #pragma unroll
    for (int o = 16; o; o >>= 1) {
        mx = fmaxf(mx, __shfl_xor_sync(0xffffffffu, mx, o));
        my = fmaxf(my, __shfl_xor_sync(0xffffffffu, my, o));
    }
    if (lane == 0) { red[w] = mx; red[w + 8] = my; }
    __syncthreads();
    if (tid == 0) {
        float MX = red[0], MY = red[8];
        #pragma unroll
        for (int i = 1; i < 8; ++i) { MX = fmaxf(MX, red[i]); MY = fmaxf(MY, red[8 + i]); }
        float cxy = MX + MY + 2.0f * sqrtf(MX * MY);
        scales[0] = cxy / 65500.0f;       scales[3] = 65500.0f / cxy;
        scales[1] = 4.0f * MX / 65500.0f; scales[4] = 65500.0f / (4.0f * MX);
        scales[2] = 4.0f * MY / 65500.0f; scales[5] = 65500.0f / (4.0f * MY);
    }
}

// ---------------- merged tensor-core cost GEMM (all three matrices, one launch) -----
__global__ void __launch_bounds__(256, 2) mma_gemm_all_kernel(
    const __nv_bfloat16* __restrict__ Xh, const __nv_bfloat16* __restrict__ Xl,
    const __nv_bfloat16* __restrict__ Yh, const __nv_bfloat16* __restrict__ Yl,
    const float* __restrict__ sqx, const float* __restrict__ sqy,
    const float* __restrict__ scales,
    u16* __restrict__ Cxy, u16* __restrict__ Cxx, u16* __restrict__ Cyy)
{
    int b = blockIdx.x;
    int which, bxi, byi;
    if (b < NCH * NCH) { which = 0; byi = b >> 6; bxi = b & 63; }
    else if (b < NCH * NCH + NTRI) { which = 1; sym_decode(b - NCH * NCH, byi, bxi); }
    else { which = 2; sym_decode(b - NCH * NCH - NTRI, byi, bxi); }

    const __nv_bfloat16* Ah_g = (which == 2) ? Yh : Xh;
    const __nv_bfloat16* Al_g = (which == 2) ? Yl : Xl;
    const __nv_bfloat16* Bh_g = (which == 1) ? Xh : Yh;
    const __nv_bfloat16* Bl_g = (which == 1) ? Xl : Yl;
    const float* sqa = (which == 2) ? sqy : sqx;
    const float* sqb = (which == 1) ? sqx : sqy;
    const float inv = scales[3 + which];
    u16* Cq = (which == 0) ? Cxy : (which == 1) ? Cxx : Cyy;

    const int bi = byi * 128, bj = bxi * 128;
    extern __shared__ __nv_bfloat16 sh[];
    __nv_bfloat16* sAh = sh;
    __nv_bfloat16* sAl = sh + 8192;
    __nv_bfloat16* sBh = sh + 16384;
    __nv_bfloat16* sBl = sh + 24576;
    const int tid = threadIdx.x;

    #pragma unroll
    for (int i = 0; i < 4; ++i) {
        int idx = tid + i * 256;
        int r = idx >> 3, c = idx & 7;
        int sc = c ^ (r & 7);
        ((uint4*)sAh)[r * 8 + sc] = *(const uint4*)(Ah_g + (u64)(bi + r) * 64 + c * 8);
        ((uint4*)sAl)[r * 8 + sc] = *(const uint4*)(Al_g + (u64)(bi + r) * 64 + c * 8);
        ((uint4*)sBh)[r * 8 + sc] = *(const uint4*)(Bh_g + (u64)(bj + r) * 64 + c * 8);
        ((uint4*)sBl)[r * 8 + sc] = *(const uint4*)(Bl_g + (u64)(bj + r) * 64 + c * 8);
    }
    __syncthreads();

    const int w = tid >> 5, lane = tid & 31;
    const int mw = (w & 3) * 32, nw = (w >> 2) * 64;
    const int lq = lane >> 3, lr = lane & 7;
    const u32 baseAh = (u32)__cvta_generic_to_shared(sAh);
    const u32 baseAl = (u32)__cvta_generic_to_shared(sAl);
    const u32 baseBh = (u32)__cvta_generic_to_shared(sBh);
    const u32 baseBl = (u32)__cvta_generic_to_shared(sBl);

    float acc[2][8][4];
    #pragma unroll
    for (int mi = 0; mi < 2; ++mi)
        #pragma unroll
        for (int ni = 0; ni < 8; ++ni)
            #pragma unroll
            for (int e = 0; e < 4; ++e) acc[mi][ni][e] = 0.f;

    #pragma unroll
    for (int ks = 0; ks < 4; ++ks) {
        const int ch = ks * 2 + (lq >> 1);
        u32 ah[2][4], al[2][4];
        #pragma unroll
        for (int mi = 0; mi < 2; ++mi) {
            int row = mw + mi * 16 + (lq & 1) * 8 + lr;
            u32 off = (u32)(row * 128 + ((ch ^ (row & 7)) << 4));
            ldsm4(ah[mi][0], ah[mi][1], ah[mi][2], ah[mi][3], baseAh + off);
            ldsm4(al[mi][0], al[mi][1], al[mi][2], al[mi][3], baseAl + off);
        }
        u32 bh[4][4], bl[4][4];
        #pragma unroll
        for (int nj = 0; nj < 4; ++nj) {
            int row = nw + nj * 16 + (lq & 1) * 8 + lr;
            u32 off = (u32)(row * 128 + ((ch ^ (row & 7)) << 4));
            ldsm4(bh[nj][0], bh[nj][1], bh[nj][2], bh[nj][3], baseBh + off);
            ldsm4(bl[nj][0], bl[nj][1], bl[nj][2], bl[nj][3], baseBl + off);
        }
        #pragma unroll
        for (int mi = 0; mi < 2; ++mi)
            #pragma unroll
            for (int ni = 0; ni < 8; ++ni) {
                int nj = ni >> 1;
                u32 h0 = (ni & 1) ? bh[nj][1] : bh[nj][0];
                u32 h1 = (ni & 1) ? bh[nj][3] : bh[nj][2];
                u32 l0 = (ni & 1) ? bl[nj][1] : bl[nj][0];
                u32 l1 = (ni & 1) ? bl[nj][3] : bl[nj][2];
                mma16816(acc[mi][ni], ah[mi], h0, h1);
                mma16816(acc[mi][ni], al[mi], h0, h1);
                mma16816(acc[mi][ni], ah[mi], l0, l1);
            }
    }

    const int tq = lane >> 2, tr = lane & 3;
    #pragma unroll
    for (int mi = 0; mi < 2; ++mi)
        #pragma unroll
        for (int rh = 0; rh < 2; ++rh) {
            int m = bi + mw + mi * 16 + rh * 8 + tq;
            float sa = sqa[m];
            #pragma unroll
            for (int ni = 0; ni < 8; ++ni) {
                int n = bj + nw + ni * 8 + tr * 2;
                float v0 = fmaxf(sa + sqb[n]     - acc[mi][ni][rh * 2 + 0], 0.f);
                float v1 = fmaxf(sa + sqb[n + 1] - acc[mi][ni][rh * 2 + 1], 0.f);
                u32 q0 = __float_as_uint(fmaf(v0, inv, 8388608.0f));
                u32 q1 = __float_as_uint(fmaf(v1, inv, 8388608.0f));
                *(u32*)(Cq + (u64)m * Nn + n) = __byte_perm(q0, q1, 0x5410);
            }
        }
}

// ---------------- merged tile softmin: all three matrices, 3 CTAs/SM ----------------
// Merge outputs are single-float chunk LSEs: out = M + lg2(S).
__global__ void __launch_bounds__(256, 3) tile_softmin_all_kernel(
    const uint4* __restrict__ Qxy, const uint4* __restrict__ Qxx, const uint4* __restrict__ Qyy,
    const float* __restrict__ faa, const float* __restrict__ gbb,
    const float* __restrict__ gab, const float* __restrict__ fba,
    const float* __restrict__ scales,
    const float* __restrict__ eps_ptr, float base_log, int init,
    float* __restrict__ pR, float* __restrict__ pC,
    float* __restrict__ pX, float* __restrict__ pY)
{
    int b = blockIdx.x;
    int which, bx, by;
    if (b < NCH * NCH) { which = 0; by = b >> 6; bx = b & 63; }
    else if (b < NCH * NCH + NTRI) { which = 1; sym_decode(b - NCH * NCH, by, bx); }
    else { which = 2; sym_decode(b - NCH * NCH - NTRI, by, bx); }

    const uint4* Q = (which == 0) ? Qxy : (which == 1) ? Qxx : Qyy;
    const float* potRow = (which == 0) ? gab : (which == 1) ? faa : gbb;
    const float* potCol = (which == 0) ? fba : (which == 1) ? faa : gbb;
    float* oR = (which == 0) ? pR : (which == 1) ? pX : pY;
    float* oC = (which == 0) ? pC : (which == 1) ? pX : pY;
    const bool doCol = (which == 0) || (by > bx);

    const int tid = threadIdx.x;
    const int c16 = tid & 15, rp = tid >> 4;

    const float s2   = L2E / (*eps_ptr);
    const float b2   = base_log * L2E;
    const float scs2 = scales[which] * s2;
    const float off  = b2 + 8388608.0f * scs2;

    __shared__ float gp[128];
    __shared__ float fp[128];
    __shared__ float2 part[128 * 17];

    uint4 qv[8];
    #pragma unroll
    for (int p = 0; p < 8; ++p)
        qv[p] = __ldcs(&Q[(u64)(by * 128 + rp + 16 * p) * 1024 + bx * 16 + c16]);

    if (tid < 128) {
        float pv = init ? 0.f : potRow[bx * 128 + tid];
        gp[tid] = fmaf(pv, s2, off);
    } else {
        int t = tid - 128;
        float pv = init ? 0.f : potCol[by * 128 + t];
        fp[t] = fmaf(pv, s2, off);
    }
    __syncthreads();

    float4 gA = *(const float4*)&gp[c16 * 8];
    float4 gB = *(const float4*)&gp[c16 * 8 + 4];
    float fpv[8];
    #pragma unroll
    for (int p = 0; p < 8; ++p) fpv[p] = fp[rp + 16 * p];

    const float nscs2 = -scs2;

    #pragma unroll
    for (int p = 0; p < 8; ++p) {
        float v0 = fmaf(q2f_lo(qv[p].x), nscs2, gA.x);
        float v1 = fmaf(q2f_hi(qv[p].x), nscs2, gA.y);
        float v2 = fmaf(q2f_lo(qv[p].y), nscs2, gA.z);
        float v3 = fmaf(q2f_hi(qv[p].y), nscs2, gA.w);
        float v4 = fmaf(q2f_lo(qv[p].z), nscs2, gB.x);
        float v5 = fmaf(q2f_hi(qv[p].z), nscs2, gB.y);
        float v6 = fmaf(q2f_lo(qv[p].w), nscs2, gB.z);
        float v7 = fmaf(q2f_hi(qv[p].w), nscs2, gB.w);
        float m = fmaxf(fmaxf(fmaxf(v0, v1), fmaxf(v2, v3)),
                        fmaxf(fmaxf(v4, v5), fmaxf(v6, v7)));
        float s = ((ex2(v0 - m) + ex2(v1 - m)) + (ex2(v2 - m) + ex2(v3 - m)))
                + ((ex2(v4 - m) + ex2(v5 - m)) + (ex2(v6 - m) + ex2(v7 - m)));
        part[(rp + 16 * p) * 17 + c16] = make_float2(m, s);
    }
    __syncthreads();

    // ---- row merge: two-sweep, single-float output (M + lg2 S) ----
    if (tid < 128) {
        float M = -3.4e38f;
        #pragma unroll
        for (int k = 0; k < 16; ++k) M = fmaxf(M, part[tid * 17 + k].x);
        float S = 0.f;
        #pragma unroll
        for (int k = 0; k < 16; ++k) {
            float2 pk = part[tid * 17 + k];
            S += pk.y * ex2(pk.x - M);
        }
        oR[(u64)bx * Nn + by * 128 + tid] = M + lg2(S);
    }

    if (doCol) {
        __syncthreads();
        #pragma unroll
        for (int e = 0; e < 8; ++e) {
            float v[8];
            #pragma unroll
            for (int p = 0; p < 8; ++p) {
                u32 a = (e < 2) ? qv[p].x : (e < 4) ? qv[p].y : (e < 6) ? qv[p].z : qv[p].w;
                float fq = (e & 1) ? q2f_hi(a) : q2f_lo(a);
                v[p] = fmaf(fq, nscs2, fpv[p]);
            }
            float m = fmaxf(fmaxf(fmaxf(v[0], v[1]), fmaxf(v[2], v[3])),
                            fmaxf(fmaxf(v[4], v[5]), fmaxf(v[6], v[7])));
            float s = ((ex2(v[0] - m) + ex2(v[1] - m)) + (ex2(v[2] - m) + ex2(v[3] - m)))
                    + ((ex2(v[4] - m) + ex2(v[5] - m)) + (ex2(v[6] - m) + ex2(v[7] - m)));
            part[(rp * 8 + e) * 17 + c16] = make_float2(m, s);
        }
        __syncthreads();
        // ---- col merge: two-sweep, single-float output ----
        if (tid < 128) {
            int e = tid & 7, cc = tid >> 3;    // col = cc*8 + e
            float M = -3.4e38f;
            #pragma unroll
            for (int k = 0; k < 16; ++k) M = fmaxf(M, part[(k * 8 + e) * 17 + cc].x);
            float S = 0.f;
            #pragma unroll
            for (int k = 0; k < 16; ++k) {
                float2 pk = part[(k * 8 + e) * 17 + cc];
                S += pk.y * ex2(pk.x - M);
            }
            int col = cc * 8 + e;
            oC[(u64)by * Nn + bx * 128 + col] = M + lg2(S);
        }
    }
}

// ---------------- combine: one output per thread, single-float partials -------------
__global__ void __launch_bounds__(256) combine_update_kernel(
    const float* __restrict__ pR, const float* __restrict__ pC,
    const float* __restrict__ pX, const float* __restrict__ pY,
    const float* __restrict__ eps_ptr, int mode,
    float* __restrict__ faa, float* __restrict__ gbb,
    float* __restrict__ gab, float* __restrict__ fba,
    float* __restrict__ tft, float* __restrict__ tgt,
    float* __restrict__ tftaa, float* __restrict__ tgtbb)
{
    const int gid = blockIdx.x * 256 + threadIdx.x;   // 0..32767
    const int p = gid >> 13;
    const int i = gid & 8191;
    const float eps = *eps_ptr;
    const float sc = -eps * LN2;

    const float* pA = (p == 0) ? pR : (p == 1) ? pC : (p == 2) ? pX : pY;

    float M = -3.4e38f;
    #pragma unroll 16
    for (int c = 0; c < NCH; ++c) M = fmaxf(M, pA[(u64)c * Nn + i]);
    float S = 0.f;
    #pragma unroll 16
    for (int c = 0; c < NCH; ++c) S += ex2(pA[(u64)c * Nn + i] - M);
    float v = sc * (M + lg2(S));

    float* dstA = (p == 0) ? fba : (p == 1) ? gab : (p == 2) ? faa : gbb;
    float* dstT = (p == 0) ? tft : (p == 1) ? tgt : (p == 2) ? tftaa : tgtbb;

    if (mode == 0)       dstA[i] = v;
    else if (mode == 1)  dstA[i] = 0.5f * (dstA[i] + v);
    else                 dstT[i] = v;
}

// ---------------- final scalar ----------------
__global__ void final_kernel(const float* __restrict__ fbaf, const float* __restrict__ faaf,
                             const float* __restrict__ gabf, const float* __restrict__ gbbf,
                             float* __restrict__ out)
{
    __shared__ float red[32];
    int tid = threadIdx.x;
    int lane = tid & 31, wid = tid >> 5;
    float s = 0.f;
    for (int i = tid; i < Nn; i += 1024)
        s += (fbaf[i] - faaf[i]) + (gabf[i] - gbbf[i]);
    #pragma unroll
    for (int o = 16; o; o >>= 1) s += __shfl_xor_sync(0xffffffffu, s, o);
    if (lane == 0) red[wid] = s;
    __syncthreads();
    if (wid == 0) {
        float v = red[lane];
        #pragma unroll
        for (int o = 16; o; o >>= 1) v += __shfl_xor_sync(0xffffffffu, v, o);
        if (lane == 0) out[0] = v / (float)Nn;
    }
}

// ---------------- launch ----------------
extern "C" void kernel_launch(void* const* d_in, const int* in_sizes, int n_in,
                              void* d_out, int out_size)
{
    const float* X   = (const float*)d_in[0];
    const float* Y   = (const float*)d_in[1];
    const float* eps = (const float*)d_in[2];
    const int n_eps  = in_sizes[2];
    float* out = (float*)d_out;

    u16 *Cxy, *Cxx, *Cyy;
    __nv_bfloat16 *Xh, *Xl, *Yh, *Yl;
    float *sqx, *sqy, *scales;
    float *faa, *gbb, *gab, *fba, *tft, *tgt, *tftaa, *tgtbb;
    float *pR, *pC, *pX, *pY;
    cudaGetSymbolAddress((void**)&Cxy, d_Cxy);
    cudaGetSymbolAddress((void**)&Cxx, d_Cxx);
    cudaGetSymbolAddress((void**)&Cyy, d_Cyy);
    cudaGetSymbolAddress((void**)&Xh, d_Xh);
    cudaGetSymbolAddress((void**)&Xl, d_Xl);
    cudaGetSymbolAddress((void**)&Yh, d_Yh);
    cudaGetSymbolAddress((void**)&Yl, d_Yl);
    cudaGetSymbolAddress((void**)&sqx, d_sqx);
    cudaGetSymbolAddress((void**)&sqy, d_sqy);
    cudaGetSymbolAddress((void**)&scales, d_scales);
    cudaGetSymbolAddress((void**)&faa, d_faa);
    cudaGetSymbolAddress((void**)&gbb, d_gbb);
    cudaGetSymbolAddress((void**)&gab, d_gab);
    cudaGetSymbolAddress((void**)&fba, d_fba);
    cudaGetSymbolAddress((void**)&tft, d_tft);
    cudaGetSymbolAddress((void**)&tgt, d_tgt);
    cudaGetSymbolAddress((void**)&tftaa, d_tftaa);
    cudaGetSymbolAddress((void**)&tgtbb, d_tgtbb);
    cudaGetSymbolAddress((void**)&pR, d_pR);
    cudaGetSymbolAddress((void**)&pC, d_pC);
    cudaGetSymbolAddress((void**)&pX, d_pX);
    cudaGetSymbolAddress((void**)&pY, d_pY);

    cudaFuncSetAttribute(mma_gemm_all_kernel,
                         cudaFuncAttributeMaxDynamicSharedMemorySize, 65536);

    const float LOGW = -logf((float)Nn);

    prep_kernel<<<2048, 256>>>(X, Y, sqx, sqy, Xh, Xl, Yh, Yl);
    scale_kernel<<<1, 256>>>(sqx, sqy, scales);
    mma_gemm_all_kernel<<<NBLK, 256, 65536>>>(Xh, Xl, Yh, Yl, sqx, sqy, scales,
                                              Cxy, Cxx, Cyy);

    for (int k = -1; k <= n_eps; ++k) {
        const float* ek = (k < 0) ? eps : (k < n_eps ? eps + k : eps + (n_eps - 1));
        int mode = (k < 0) ? 0 : (k < n_eps ? 1 : 2);
        int init = (k < 0) ? 1 : 0;
        tile_softmin_all_kernel<<<NBLK, 256>>>(
            (const uint4*)Cxy, (const uint4*)Cxx, (const uint4*)Cyy,
            faa, gbb, gab, fba, scales, ek, LOGW, init,
            pR, pC, pX, pY);
        combine_update_kernel<<<128, 256>>>(
            pR, pC, pX, pY, ek, mode,
            faa, gbb, gab, fba, tft, tgt, tftaa, tgtbb);
    }

    final_kernel<<<1, 1024>>>(tft, tftaa, tgt, tgtbb, out);
}